// round 11
// baseline (speedup 1.0000x reference)
#include <cuda_runtime.h>
#include <math.h>

#define BB 8
#define HH 1024
#define LL 2048
#define NN 64
#define NF 4096
#define PADI(i) ((i) + ((i) >> 4))
#define BUFSZ 4352

__device__ float2 g_cden[LL * NN];
__device__ float4 g_cd4[LL * NN];              // (cden, c*cden) interleaved
__device__ float2 g_fl[LL];
__device__ float2 g_cl[LL];
__device__ float2 g_ar[(size_t)HH * LL];       // 16 MB
__device__ float2 g_Kf[(size_t)HH * NF];       // 32 MB (pre-scaled by 1/NF)
__device__ float2 g_tw[1025];
__device__ float2 g_rT[(size_t)BB * 512 * LL]; // 64 MB
__device__ float2 g_oT[(size_t)BB * 512 * LL]; // 64 MB

__device__ __forceinline__ float2 cmulf(float2 a, float2 b) {
    return make_float2(fmaf(a.x, b.x, -a.y * b.y), fmaf(a.x, b.y, a.y * b.x));
}
__device__ __forceinline__ void cfma(float2& acc, float2 a, float2 b) {
    acc.x = fmaf(a.x, b.x, fmaf(-a.y, b.y, acc.x));
    acc.y = fmaf(a.x, b.y, fmaf(a.y, b.x, acc.y));
}
__device__ __forceinline__ float2 cadd(float2 a, float2 b) { return make_float2(a.x + b.x, a.y + b.y); }
__device__ __forceinline__ float2 csub(float2 a, float2 b) { return make_float2(a.x - b.x, a.y - b.y); }

template <int DIR>
__device__ __forceinline__ void dft4v(float2 v[4]) {
    float2 apc = cadd(v[0], v[2]), amc = csub(v[0], v[2]);
    float2 bpd = cadd(v[1], v[3]), bmd = csub(v[1], v[3]);
    float2 jb = make_float2(-(float)DIR * bmd.y, (float)DIR * bmd.x);
    v[0] = cadd(apc, bpd); v[1] = cadd(amc, jb);
    v[2] = csub(apc, bpd); v[3] = csub(amc, jb);
}

template <int DIR>
__device__ __forceinline__ void dft8(float2 v[8]) {
    float2 e[4] = {v[0], v[2], v[4], v[6]};
    float2 o[4] = {v[1], v[3], v[5], v[7]};
    dft4v<DIR>(e);
    dft4v<DIR>(o);
    const float R2 = 0.70710678118654752440f;
    float2 w1 = make_float2(R2, (float)DIR * R2);
    float2 w3 = make_float2(-R2, (float)DIR * R2);
    float2 o1 = cmulf(o[1], w1);
    float2 o2 = make_float2(-(float)DIR * o[2].y, (float)DIR * o[2].x);
    float2 o3 = cmulf(o[3], w3);
    v[0] = cadd(e[0], o[0]); v[4] = csub(e[0], o[0]);
    v[1] = cadd(e[1], o1);   v[5] = csub(e[1], o1);
    v[2] = cadd(e[2], o2);   v[6] = csub(e[2], o2);
    v[3] = cadd(e[3], o3);   v[7] = csub(e[3], o3);
}

__device__ __forceinline__ void pass_store(float2* dst, float2 v[8], int ob, int ls, float2 w1) {
    dst[PADI(ob)] = v[0];
    float2 wk = w1;
    dst[PADI(ob + (1 << ls))] = cmulf(v[1], wk);
#pragma unroll
    for (int k = 2; k < 8; k++) {
        wk = cmulf(wk, w1);
        dst[PADI(ob + (k << ls))] = cmulf(v[k], wk);
    }
}

template <int NTOT, int DIR, int NT>
__device__ __forceinline__ void fft_passes(float2*& src, float2*& dst, int nn, int ls, int nnEnd) {
    while (nn >= nnEnd) {
        int tstep = NF / nn;
        for (int idx = threadIdx.x; idx < (NTOT >> 3); idx += NT) {
            int p = idx >> ls;
            int q = idx & ((1 << ls) - 1);
            int base = q + (p << ls);
            float2 v[8];
#pragma unroll
            for (int j = 0; j < 8; j++) v[j] = src[PADI(base + j * (NTOT >> 3))];
            dft8<DIR>(v);
            float2 w1 = __ldg(&g_tw[p * tstep]);
            if (DIR > 0) w1.y = -w1.y;
            pass_store(dst, v, q + (p << (ls + 3)), ls, w1);
        }
        __syncthreads();
        float2* t = src; src = dst; dst = t;
        nn >>= 3;
        ls += 3;
    }
}

template <int NFFT, int DIR, int NT>
__device__ __forceinline__ void block_fft(float2* x, float2* y) {
    float2* src = x;
    float2* dst = y;
    fft_passes<NFFT, DIR, NT>(src, dst, NFFT, 0, 8);
    if (NFFT == LL) {  // radix-4 tail, nn=4, ls=9
        for (int idx = threadIdx.x; idx < (NFFT >> 2); idx += NT) {
            float2 v[4];
#pragma unroll
            for (int j = 0; j < 4; j++) v[j] = src[PADI(idx + j * (NFFT >> 2))];
            dft4v<DIR>(v);
#pragma unroll
            for (int k = 0; k < 4; k++) dst[PADI(idx + (k << 9))] = v[k];
        }
        __syncthreads();
    }
}

__global__ void k_tw() {
    int j = blockIdx.x * blockDim.x + threadIdx.x;
    if (j > 1024) return;
    float ang = -6.28318530717958647692f * (float)j / (float)NF;
    float s, c;
    sincosf(ang, &s, &c);
    g_tw[j] = make_float2(c, s);
}

__global__ void k_prep(const float* __restrict__ B_re, const float* __restrict__ B_im,
                       const float* __restrict__ P_re, const float* __restrict__ P_im,
                       const float* __restrict__ Q_re, const float* __restrict__ Q_im,
                       const float* __restrict__ dre,  const float* __restrict__ dim_,
                       const float* __restrict__ step) {
    int l = blockIdx.x * blockDim.x + threadIdx.x;
    if (l >= LL) return;
    float st = fmaxf(step[0], 1e-6f);
    float ang = (-6.28318530717958647692f * (float)l) / (float)LL;
    float zs, zc;
    sincosf(ang, &zs, &zc);
    float2 omz = make_float2(1.0f - zc, -zs);
    float2 opz = make_float2(1.0f + zc, zs);
    float invp = 1.0f / (opz.x * opz.x + opz.y * opz.y);
    float2 q = cmulf(omz, make_float2(opz.x, -opz.y));
    float2 g = make_float2((2.0f / st) * q.x * invp, (2.0f / st) * q.y * invp);
    float2 k10 = make_float2(0.f, 0.f), k11 = make_float2(0.f, 0.f);
    for (int n = 0; n < NN; n++) {
        float2 den = make_float2(g.x - dre[n], g.y - dim_[n]);
        float di = 1.0f / (den.x * den.x + den.y * den.y);
        float2 cd = make_float2(den.x * di, -den.y * di);
        g_cden[(size_t)l * NN + n] = cd;
        float2 Bv = make_float2(B_re[n], B_im[n]);
        float2 Pv = make_float2(P_re[n], P_im[n]);
        float2 Qv = make_float2(Q_re[n], Q_im[n]);
        cfma(k10, cmulf(Qv, Bv), cd);
        cfma(k11, cmulf(Qv, Pv), cd);
    }
    float2 onep = make_float2(1.0f + k11.x, k11.y);
    float i2 = 1.0f / (onep.x * onep.x + onep.y * onep.y);
    float2 c = cmulf(k10, make_float2(onep.x * i2, -onep.y * i2));
    g_fl[l] = make_float2(2.0f * opz.x * invp, -2.0f * opz.y * invp);
    g_cl[l] = c;
    for (int n = 0; n < NN; n++) {
        float2 cd = g_cden[(size_t)l * NN + n];
        float2 cd2 = cmulf(c, cd);
        g_cd4[(size_t)l * NN + n] = make_float4(cd.x, cd.y, cd2.x, cd2.y);
    }
}

// K2: at_roots[h,l] = f[l] * sum_n (CB[h,n]*cden[l,n] - CP[h,n]*cden2[l,n])
// tile 64l x 64h, 4x4 microtile, single accumulator per (h,l), float4 smem
__global__ void __launch_bounds__(256, 3) k_ar(const float* __restrict__ C_re, const float* __restrict__ C_im,
                                               const float* __restrict__ B_re, const float* __restrict__ B_im,
                                               const float* __restrict__ P_re, const float* __restrict__ P_im) {
    __shared__ float4 sCD[16 * 65];   // [n][l]: (cden, cden2)
    __shared__ float4 sBP[16 * 65];   // [n][h]: (CB, CP)
    int l0 = blockIdx.x * 64;
    int h0 = blockIdx.y * 64;
    int tid = threadIdx.x;
    int tl = (tid & 15) * 4;
    int th = (tid >> 4) * 4;
    float2 acc[4][4];
#pragma unroll
    for (int ih = 0; ih < 4; ih++)
#pragma unroll
        for (int il = 0; il < 4; il++) acc[ih][il] = make_float2(0.f, 0.f);

    for (int nc = 0; nc < NN; nc += 16) {
        __syncthreads();
        for (int i = tid; i < 64 * 16; i += 256) {
            int row = i >> 4, n = i & 15;
            int gn = nc + n;
            sCD[n * 65 + row] = g_cd4[(size_t)(l0 + row) * NN + gn];
            float2 Cv = make_float2(C_re[(size_t)(h0 + row) * NN + gn], C_im[(size_t)(h0 + row) * NN + gn]);
            float2 cb = cmulf(Cv, make_float2(B_re[gn], B_im[gn]));
            float2 cp = cmulf(Cv, make_float2(P_re[gn], P_im[gn]));
            sBP[n * 65 + row] = make_float4(cb.x, cb.y, cp.x, cp.y);
        }
        __syncthreads();
#pragma unroll
        for (int n = 0; n < 16; n++) {
            float4 cd[4], bp[4];
#pragma unroll
            for (int il = 0; il < 4; il++) cd[il] = sCD[n * 65 + tl + il];
#pragma unroll
            for (int ih = 0; ih < 4; ih++) bp[ih] = sBP[n * 65 + th + ih];
#pragma unroll
            for (int ih = 0; ih < 4; ih++)
#pragma unroll
                for (int il = 0; il < 4; il++) {
                    float2& a = acc[ih][il];
                    a.x = fmaf(bp[ih].x, cd[il].x, a.x);
                    a.x = fmaf(-bp[ih].y, cd[il].y, a.x);
                    a.x = fmaf(-bp[ih].z, cd[il].z, a.x);
                    a.x = fmaf(bp[ih].w, cd[il].w, a.x);
                    a.y = fmaf(bp[ih].x, cd[il].y, a.y);
                    a.y = fmaf(bp[ih].y, cd[il].x, a.y);
                    a.y = fmaf(-bp[ih].z, cd[il].w, a.y);
                    a.y = fmaf(-bp[ih].w, cd[il].z, a.y);
                }
        }
    }
    float2 fl[4];
#pragma unroll
    for (int il = 0; il < 4; il++) fl[il] = g_fl[l0 + tl + il];
#pragma unroll
    for (int ih = 0; ih < 4; ih++) {
        float2 res[4];
#pragma unroll
        for (int il = 0; il < 4; il++) res[il] = cmulf(fl[il], acc[ih][il]);
        float4* dst = (float4*)(g_ar + (size_t)(h0 + th + ih) * LL + l0 + tl);
        dst[0] = make_float4(res[0].x, res[0].y, res[1].x, res[1].y);
        dst[1] = make_float4(res[2].x, res[2].y, res[3].x, res[3].y);
    }
}

__global__ void __launch_bounds__(512, 2) k_kf() {
    extern __shared__ float2 sh2[];
    float2* A = sh2;
    float2* Bb = sh2 + BUFSZ;
    int h = blockIdx.x;
    for (int l = threadIdx.x; l < LL; l += 512) A[PADI(l)] = g_ar[(size_t)h * LL + l];
    __syncthreads();
    block_fft<LL, 1, 512>(A, Bb);
    float kv[4];
#pragma unroll
    for (int i = 0; i < 4; i++) {
        int l = threadIdx.x + i * 512;
        kv[i] = A[PADI(l)].x * (1.0f / (float)LL);
    }
    __syncthreads();
#pragma unroll
    for (int i = 0; i < 4; i++) {
        int l = threadIdx.x + i * 512;
        A[PADI(l)] = make_float2(kv[i], 0.f);
        A[PADI(l + LL)] = make_float2(0.f, 0.f);
    }
    __syncthreads();
    block_fft<NF, -1, 512>(A, Bb);
    const float sc = 1.0f / (float)NF;   // pre-scale spectrum
    for (int k = threadIdx.x; k < NF; k += 512) {
        float2 v = A[PADI(k)];
        g_Kf[(size_t)h * NF + k] = make_float2(v.x * sc, v.y * sc);
    }
}

__global__ void __launch_bounds__(256) k_tri(const float* __restrict__ r) {
    __shared__ float2 s[32][33];
    int b = blockIdx.z, l0 = blockIdx.x * 32, hp0 = blockIdx.y * 32;
    const float2* r2 = (const float2*)(r + (size_t)b * LL * HH);
    int lane = threadIdx.x & 31, row = threadIdx.x >> 5;
#pragma unroll
    for (int k = 0; k < 4; k++) {
        int rr = row + 8 * k;
        s[rr][lane] = r2[(size_t)(l0 + rr) * 512 + hp0 + lane];
    }
    __syncthreads();
    float2* dst = g_rT + (size_t)b * 512 * LL;
#pragma unroll
    for (int k = 0; k < 4; k++) {
        int rr = row + 8 * k;
        dst[(size_t)(hp0 + rr) * LL + l0 + lane] = s[lane][rr];
    }
}

__global__ void __launch_bounds__(256) k_tro(float* __restrict__ out) {
    __shared__ float2 s[32][33];
    int b = blockIdx.z, l0 = blockIdx.x * 32, hp0 = blockIdx.y * 32;
    const float2* src = g_oT + (size_t)b * 512 * LL;
    int lane = threadIdx.x & 31, row = threadIdx.x >> 5;
#pragma unroll
    for (int k = 0; k < 4; k++) {
        int rr = row + 8 * k;
        s[rr][lane] = src[(size_t)(hp0 + rr) * LL + l0 + lane];
    }
    __syncthreads();
    float2* o2 = (float2*)(out + (size_t)b * LL * HH);
#pragma unroll
    for (int k = 0; k < 4; k++) {
        int rr = row + 8 * k;
        o2[(size_t)(l0 + rr) * 512 + hp0 + lane] = s[lane][rr];
    }
}

__global__ void __launch_bounds__(512, 2) k_conv(const float* __restrict__ Dp) {
    extern __shared__ float2 sh2[];
    float2* A = sh2;
    float2* Bb = sh2 + BUFSZ;
    int hp = blockIdx.x;
    int b = blockIdx.y;
    int tid = threadIdx.x;
    float Dv = Dp[0];
    const float2* rp = g_rT + ((size_t)b * 512 + hp) * LL;
    float2 rv[4];
    float2 v[8];
#pragma unroll
    for (int j = 0; j < 4; j++) {
        rv[j] = rp[tid + j * 512];
        v[j] = rv[j];
        v[j + 4] = make_float2(0.f, 0.f);
    }
    dft8<-1>(v);
    pass_store(A, v, tid << 3, 0, __ldg(&g_tw[tid]));
    __syncthreads();
    float2* src = A;
    float2* dst = Bb;
    fft_passes<NF, -1, 512>(src, dst, 512, 3, 8);
    {
        const float2* K0 = g_Kf + (size_t)(2 * hp) * NF;
        const float2* K1 = K0 + NF;
        float2* W = src;
        for (int k = tid; k <= NF / 2; k += 512) {
            int km = (NF - k) & (NF - 1);
            float2 a = W[PADI(k)];
            float2 bc = W[PADI(km)]; bc.y = -bc.y;
            float2 X0 = make_float2(0.5f * (a.x + bc.x), 0.5f * (a.y + bc.y));
            float2 dd = make_float2(0.5f * (a.x - bc.x), 0.5f * (a.y - bc.y));
            float2 X1 = make_float2(dd.y, -dd.x);
            float2 t0 = cmulf(X0, __ldg(&K0[k]));
            float2 t1 = cmulf(X1, __ldg(&K1[k]));
            W[PADI(k)]  = make_float2(t0.x - t1.y, t0.y + t1.x);
            W[PADI(km)] = make_float2(t0.x + t1.y, -t0.y + t1.x);
        }
    }
    __syncthreads();
    fft_passes<NF, 1, 512>(src, dst, NF, 0, 64);
#pragma unroll
    for (int j = 0; j < 8; j++) v[j] = src[PADI(tid + j * 512)];
    dft8<1>(v);
    float2* op = g_oT + ((size_t)b * 512 + hp) * LL;
#pragma unroll
    for (int k = 0; k < 4; k++) {
        float y0 = fmaf(Dv, rv[k].x, v[k].x);   // Kf pre-scaled by 1/NF
        float y1 = fmaf(Dv, rv[k].y, v[k].y);
        float g0 = 0.5f * y0 * (1.0f + erff(y0 * 0.70710678118654752f));
        float g1 = 0.5f * y1 * (1.0f + erff(y1 * 0.70710678118654752f));
        op[tid + k * 512] = make_float2(g0, g1);
    }
}

extern "C" void kernel_launch(void* const* d_in, const int* in_sizes, int n_in,
                              void* d_out, int out_size) {
    const float* r    = (const float*)d_in[0];
    const float* B_re = (const float*)d_in[1];
    const float* B_im = (const float*)d_in[2];
    const float* C_re = (const float*)d_in[3];
    const float* C_im = (const float*)d_in[4];
    const float* P_re = (const float*)d_in[5];
    const float* P_im = (const float*)d_in[6];
    const float* Q_re = (const float*)d_in[7];
    const float* Q_im = (const float*)d_in[8];
    const float* dre  = (const float*)d_in[9];
    const float* dim_ = (const float*)d_in[10];
    const float* step = (const float*)d_in[11];
    const float* Dp   = (const float*)d_in[12];
    float* out = (float*)d_out;

    static int attr_done = 0;
    if (!attr_done) {
        cudaFuncSetAttribute(k_kf,   cudaFuncAttributeMaxDynamicSharedMemorySize, 2 * BUFSZ * sizeof(float2));
        cudaFuncSetAttribute(k_conv, cudaFuncAttributeMaxDynamicSharedMemorySize, 2 * BUFSZ * sizeof(float2));
        attr_done = 1;
    }

    k_tw<<<5, 256>>>();
    k_prep<<<8, 256>>>(B_re, B_im, P_re, P_im, Q_re, Q_im, dre, dim_, step);
    k_tri<<<dim3(LL / 32, 16, BB), 256>>>(r);
    k_ar<<<dim3(LL / 64, HH / 64), 256>>>(C_re, C_im, B_re, B_im, P_re, P_im);
    k_kf<<<HH, 512, 2 * BUFSZ * sizeof(float2)>>>();
    k_conv<<<dim3(HH / 2, BB), 512, 2 * BUFSZ * sizeof(float2)>>>(Dp);
    k_tro<<<dim3(LL / 32, 16, BB), 256>>>(out);
}

// round 12
// speedup vs baseline: 1.1283x; 1.1283x over previous
#include <cuda_runtime.h>
#include <math.h>

#define BB 8
#define HH 1024
#define LL 2048
#define NN 64
#define NF 4096
#define PADI(i) ((i) + ((i) >> 4))
#define BUFSZ 4352

__device__ float2 g_cden[LL * NN];
__device__ float4 g_cd4[LL * NN];              // (cden, c*cden) interleaved
__device__ float2 g_fl[LL];
__device__ float2 g_cl[LL];
__device__ float2 g_ar[(size_t)HH * LL];       // 16 MB
__device__ float2 g_Kf[(size_t)HH * NF];       // 32 MB (pre-scaled by 1/NF)
__device__ float2 g_tw[1025];
__device__ float2 g_rT[(size_t)BB * 512 * LL]; // 64 MB
__device__ float2 g_oT[(size_t)BB * 512 * LL]; // 64 MB

__device__ __forceinline__ float2 cmulf(float2 a, float2 b) {
    return make_float2(fmaf(a.x, b.x, -a.y * b.y), fmaf(a.x, b.y, a.y * b.x));
}
__device__ __forceinline__ void cfma(float2& acc, float2 a, float2 b) {
    acc.x = fmaf(a.x, b.x, fmaf(-a.y, b.y, acc.x));
    acc.y = fmaf(a.x, b.y, fmaf(a.y, b.x, acc.y));
}
__device__ __forceinline__ float2 cadd(float2 a, float2 b) { return make_float2(a.x + b.x, a.y + b.y); }
__device__ __forceinline__ float2 csub(float2 a, float2 b) { return make_float2(a.x - b.x, a.y - b.y); }

template <int DIR>
__device__ __forceinline__ void dft4v(float2 v[4]) {
    float2 apc = cadd(v[0], v[2]), amc = csub(v[0], v[2]);
    float2 bpd = cadd(v[1], v[3]), bmd = csub(v[1], v[3]);
    float2 jb = make_float2(-(float)DIR * bmd.y, (float)DIR * bmd.x);
    v[0] = cadd(apc, bpd); v[1] = cadd(amc, jb);
    v[2] = csub(apc, bpd); v[3] = csub(amc, jb);
}

template <int DIR>
__device__ __forceinline__ void dft8(float2 v[8]) {
    float2 e[4] = {v[0], v[2], v[4], v[6]};
    float2 o[4] = {v[1], v[3], v[5], v[7]};
    dft4v<DIR>(e);
    dft4v<DIR>(o);
    const float R2 = 0.70710678118654752440f;
    float2 w1 = make_float2(R2, (float)DIR * R2);
    float2 w3 = make_float2(-R2, (float)DIR * R2);
    float2 o1 = cmulf(o[1], w1);
    float2 o2 = make_float2(-(float)DIR * o[2].y, (float)DIR * o[2].x);
    float2 o3 = cmulf(o[3], w3);
    v[0] = cadd(e[0], o[0]); v[4] = csub(e[0], o[0]);
    v[1] = cadd(e[1], o1);   v[5] = csub(e[1], o1);
    v[2] = cadd(e[2], o2);   v[6] = csub(e[2], o2);
    v[3] = cadd(e[3], o3);   v[7] = csub(e[3], o3);
}

__device__ __forceinline__ void pass_store(float2* dst, float2 v[8], int ob, int ls, float2 w1) {
    dst[PADI(ob)] = v[0];
    float2 wk = w1;
    dst[PADI(ob + (1 << ls))] = cmulf(v[1], wk);
#pragma unroll
    for (int k = 2; k < 8; k++) {
        wk = cmulf(wk, w1);
        dst[PADI(ob + (k << ls))] = cmulf(v[k], wk);
    }
}

template <int NTOT, int DIR, int NT>
__device__ __forceinline__ void fft_passes(float2*& src, float2*& dst, int nn, int ls, int nnEnd) {
    while (nn >= nnEnd) {
        int tstep = NF / nn;
        for (int idx = threadIdx.x; idx < (NTOT >> 3); idx += NT) {
            int p = idx >> ls;
            int q = idx & ((1 << ls) - 1);
            int base = q + (p << ls);
            float2 v[8];
#pragma unroll
            for (int j = 0; j < 8; j++) v[j] = src[PADI(base + j * (NTOT >> 3))];
            dft8<DIR>(v);
            float2 w1 = __ldg(&g_tw[p * tstep]);
            if (DIR > 0) w1.y = -w1.y;
            pass_store(dst, v, q + (p << (ls + 3)), ls, w1);
        }
        __syncthreads();
        float2* t = src; src = dst; dst = t;
        nn >>= 3;
        ls += 3;
    }
}

template <int NFFT, int DIR, int NT>
__device__ __forceinline__ void block_fft(float2* x, float2* y) {
    float2* src = x;
    float2* dst = y;
    fft_passes<NFFT, DIR, NT>(src, dst, NFFT, 0, 8);
    if (NFFT == LL) {  // radix-4 tail, nn=4, ls=9
        for (int idx = threadIdx.x; idx < (NFFT >> 2); idx += NT) {
            float2 v[4];
#pragma unroll
            for (int j = 0; j < 4; j++) v[j] = src[PADI(idx + j * (NFFT >> 2))];
            dft4v<DIR>(v);
#pragma unroll
            for (int k = 0; k < 4; k++) dst[PADI(idx + (k << 9))] = v[k];
        }
        __syncthreads();
    }
}

__global__ void k_tw() {
    int j = blockIdx.x * blockDim.x + threadIdx.x;
    if (j > 1024) return;
    float ang = -6.28318530717958647692f * (float)j / (float)NF;
    float s, c;
    sincosf(ang, &s, &c);
    g_tw[j] = make_float2(c, s);
}

__global__ void k_prep(const float* __restrict__ B_re, const float* __restrict__ B_im,
                       const float* __restrict__ P_re, const float* __restrict__ P_im,
                       const float* __restrict__ Q_re, const float* __restrict__ Q_im,
                       const float* __restrict__ dre,  const float* __restrict__ dim_,
                       const float* __restrict__ step) {
    int l = blockIdx.x * blockDim.x + threadIdx.x;
    if (l >= LL) return;
    float st = fmaxf(step[0], 1e-6f);
    float ang = (-6.28318530717958647692f * (float)l) / (float)LL;
    float zs, zc;
    sincosf(ang, &zs, &zc);
    float2 omz = make_float2(1.0f - zc, -zs);
    float2 opz = make_float2(1.0f + zc, zs);
    float invp = 1.0f / (opz.x * opz.x + opz.y * opz.y);
    float2 q = cmulf(omz, make_float2(opz.x, -opz.y));
    float2 g = make_float2((2.0f / st) * q.x * invp, (2.0f / st) * q.y * invp);
    float2 k10 = make_float2(0.f, 0.f), k11 = make_float2(0.f, 0.f);
    for (int n = 0; n < NN; n++) {
        float2 den = make_float2(g.x - dre[n], g.y - dim_[n]);
        float di = 1.0f / (den.x * den.x + den.y * den.y);
        float2 cd = make_float2(den.x * di, -den.y * di);
        g_cden[(size_t)l * NN + n] = cd;
        float2 Bv = make_float2(B_re[n], B_im[n]);
        float2 Pv = make_float2(P_re[n], P_im[n]);
        float2 Qv = make_float2(Q_re[n], Q_im[n]);
        cfma(k10, cmulf(Qv, Bv), cd);
        cfma(k11, cmulf(Qv, Pv), cd);
    }
    float2 onep = make_float2(1.0f + k11.x, k11.y);
    float i2 = 1.0f / (onep.x * onep.x + onep.y * onep.y);
    float2 c = cmulf(k10, make_float2(onep.x * i2, -onep.y * i2));
    g_fl[l] = make_float2(2.0f * opz.x * invp, -2.0f * opz.y * invp);
    g_cl[l] = c;
    for (int n = 0; n < NN; n++) {
        float2 cd = g_cden[(size_t)l * NN + n];
        float2 cd2 = cmulf(c, cd);
        g_cd4[(size_t)l * NN + n] = make_float4(cd.x, cd.y, cd2.x, cd2.y);
    }
}

// K2: at_roots[h,l] = f[l] * sum_n (CB[h,n]*cden[l,n] - CP[h,n]*cden2[l,n])
// tile 64l x 64h, STRIDED 4x4 microtile (stride 16 -> conflict-free LDS.128)
__global__ void __launch_bounds__(256, 3) k_ar(const float* __restrict__ C_re, const float* __restrict__ C_im,
                                               const float* __restrict__ B_re, const float* __restrict__ B_im,
                                               const float* __restrict__ P_re, const float* __restrict__ P_im) {
    __shared__ float4 sCD[16 * 65];   // [n][l]: (cden, cden2)
    __shared__ float4 sBP[16 * 65];   // [n][h]: (CB, CP)
    int l0 = blockIdx.x * 64;
    int h0 = blockIdx.y * 64;
    int tid = threadIdx.x;
    int tl = tid & 15;    // l lane: handles l0 + tl + 16*il
    int th = tid >> 4;    // h lane: handles h0 + th + 16*ih
    float2 acc[4][4];
#pragma unroll
    for (int ih = 0; ih < 4; ih++)
#pragma unroll
        for (int il = 0; il < 4; il++) acc[ih][il] = make_float2(0.f, 0.f);

    for (int nc = 0; nc < NN; nc += 16) {
        __syncthreads();
        for (int i = tid; i < 64 * 16; i += 256) {
            int row = i >> 4, n = i & 15;
            int gn = nc + n;
            sCD[n * 65 + row] = g_cd4[(size_t)(l0 + row) * NN + gn];
            float2 Cv = make_float2(C_re[(size_t)(h0 + row) * NN + gn], C_im[(size_t)(h0 + row) * NN + gn]);
            float2 cb = cmulf(Cv, make_float2(B_re[gn], B_im[gn]));
            float2 cp = cmulf(Cv, make_float2(P_re[gn], P_im[gn]));
            sBP[n * 65 + row] = make_float4(cb.x, cb.y, cp.x, cp.y);
        }
        __syncthreads();
#pragma unroll
        for (int n = 0; n < 16; n++) {
            float4 cd[4], bp[4];
#pragma unroll
            for (int il = 0; il < 4; il++) cd[il] = sCD[n * 65 + tl + 16 * il];
#pragma unroll
            for (int ih = 0; ih < 4; ih++) bp[ih] = sBP[n * 65 + th + 16 * ih];
#pragma unroll
            for (int ih = 0; ih < 4; ih++)
#pragma unroll
                for (int il = 0; il < 4; il++) {
                    float2& a = acc[ih][il];
                    a.x = fmaf(bp[ih].x, cd[il].x, a.x);
                    a.x = fmaf(-bp[ih].y, cd[il].y, a.x);
                    a.x = fmaf(-bp[ih].z, cd[il].z, a.x);
                    a.x = fmaf(bp[ih].w, cd[il].w, a.x);
                    a.y = fmaf(bp[ih].x, cd[il].y, a.y);
                    a.y = fmaf(bp[ih].y, cd[il].x, a.y);
                    a.y = fmaf(-bp[ih].z, cd[il].w, a.y);
                    a.y = fmaf(-bp[ih].w, cd[il].z, a.y);
                }
        }
    }
    float2 fl[4];
#pragma unroll
    for (int il = 0; il < 4; il++) fl[il] = g_fl[l0 + tl + 16 * il];
#pragma unroll
    for (int ih = 0; ih < 4; ih++) {
        int h = h0 + th + 16 * ih;
#pragma unroll
        for (int il = 0; il < 4; il++) {
            g_ar[(size_t)h * LL + l0 + tl + 16 * il] = cmulf(fl[il], acc[ih][il]);
        }
    }
}

__global__ void __launch_bounds__(512, 2) k_kf() {
    extern __shared__ float2 sh2[];
    float2* A = sh2;
    float2* Bb = sh2 + BUFSZ;
    int h = blockIdx.x;
    for (int l = threadIdx.x; l < LL; l += 512) A[PADI(l)] = g_ar[(size_t)h * LL + l];
    __syncthreads();
    block_fft<LL, 1, 512>(A, Bb);
    float kv[4];
#pragma unroll
    for (int i = 0; i < 4; i++) {
        int l = threadIdx.x + i * 512;
        kv[i] = A[PADI(l)].x * (1.0f / (float)LL);
    }
    __syncthreads();
#pragma unroll
    for (int i = 0; i < 4; i++) {
        int l = threadIdx.x + i * 512;
        A[PADI(l)] = make_float2(kv[i], 0.f);
        A[PADI(l + LL)] = make_float2(0.f, 0.f);
    }
    __syncthreads();
    block_fft<NF, -1, 512>(A, Bb);
    const float sc = 1.0f / (float)NF;   // pre-scale spectrum
    for (int k = threadIdx.x; k < NF; k += 512) {
        float2 v = A[PADI(k)];
        g_Kf[(size_t)h * NF + k] = make_float2(v.x * sc, v.y * sc);
    }
}

__global__ void __launch_bounds__(256) k_tri(const float* __restrict__ r) {
    __shared__ float2 s[32][33];
    int b = blockIdx.z, l0 = blockIdx.x * 32, hp0 = blockIdx.y * 32;
    const float2* r2 = (const float2*)(r + (size_t)b * LL * HH);
    int lane = threadIdx.x & 31, row = threadIdx.x >> 5;
#pragma unroll
    for (int k = 0; k < 4; k++) {
        int rr = row + 8 * k;
        s[rr][lane] = r2[(size_t)(l0 + rr) * 512 + hp0 + lane];
    }
    __syncthreads();
    float2* dst = g_rT + (size_t)b * 512 * LL;
#pragma unroll
    for (int k = 0; k < 4; k++) {
        int rr = row + 8 * k;
        dst[(size_t)(hp0 + rr) * LL + l0 + lane] = s[lane][rr];
    }
}

__global__ void __launch_bounds__(256) k_tro(float* __restrict__ out) {
    __shared__ float2 s[32][33];
    int b = blockIdx.z, l0 = blockIdx.x * 32, hp0 = blockIdx.y * 32;
    const float2* src = g_oT + (size_t)b * 512 * LL;
    int lane = threadIdx.x & 31, row = threadIdx.x >> 5;
#pragma unroll
    for (int k = 0; k < 4; k++) {
        int rr = row + 8 * k;
        s[rr][lane] = src[(size_t)(hp0 + rr) * LL + l0 + lane];
    }
    __syncthreads();
    float2* o2 = (float2*)(out + (size_t)b * LL * HH);
#pragma unroll
    for (int k = 0; k < 4; k++) {
        int rr = row + 8 * k;
        o2[(size_t)(l0 + rr) * 512 + hp0 + lane] = s[lane][rr];
    }
}

__global__ void __launch_bounds__(512, 2) k_conv(const float* __restrict__ Dp) {
    extern __shared__ float2 sh2[];
    float2* A = sh2;
    float2* Bb = sh2 + BUFSZ;
    int hp = blockIdx.x;
    int b = blockIdx.y;
    int tid = threadIdx.x;
    float Dv = Dp[0];
    const float2* rp = g_rT + ((size_t)b * 512 + hp) * LL;
    float2 rv[4];
    float2 v[8];
#pragma unroll
    for (int j = 0; j < 4; j++) {
        rv[j] = rp[tid + j * 512];
        v[j] = rv[j];
        v[j + 4] = make_float2(0.f, 0.f);
    }
    dft8<-1>(v);
    pass_store(A, v, tid << 3, 0, __ldg(&g_tw[tid]));
    __syncthreads();
    float2* src = A;
    float2* dst = Bb;
    fft_passes<NF, -1, 512>(src, dst, 512, 3, 8);
    {
        const float2* K0 = g_Kf + (size_t)(2 * hp) * NF;
        const float2* K1 = K0 + NF;
        float2* W = src;
        for (int k = tid; k <= NF / 2; k += 512) {
            int km = (NF - k) & (NF - 1);
            float2 a = W[PADI(k)];
            float2 bc = W[PADI(km)]; bc.y = -bc.y;
            float2 X0 = make_float2(0.5f * (a.x + bc.x), 0.5f * (a.y + bc.y));
            float2 dd = make_float2(0.5f * (a.x - bc.x), 0.5f * (a.y - bc.y));
            float2 X1 = make_float2(dd.y, -dd.x);
            float2 t0 = cmulf(X0, __ldg(&K0[k]));
            float2 t1 = cmulf(X1, __ldg(&K1[k]));
            W[PADI(k)]  = make_float2(t0.x - t1.y, t0.y + t1.x);
            W[PADI(km)] = make_float2(t0.x + t1.y, -t0.y + t1.x);
        }
    }
    __syncthreads();
    fft_passes<NF, 1, 512>(src, dst, NF, 0, 64);
#pragma unroll
    for (int j = 0; j < 8; j++) v[j] = src[PADI(tid + j * 512)];
    dft8<1>(v);
    float2* op = g_oT + ((size_t)b * 512 + hp) * LL;
#pragma unroll
    for (int k = 0; k < 4; k++) {
        float y0 = fmaf(Dv, rv[k].x, v[k].x);   // Kf pre-scaled by 1/NF
        float y1 = fmaf(Dv, rv[k].y, v[k].y);
        float g0 = 0.5f * y0 * (1.0f + erff(y0 * 0.70710678118654752f));
        float g1 = 0.5f * y1 * (1.0f + erff(y1 * 0.70710678118654752f));
        op[tid + k * 512] = make_float2(g0, g1);
    }
}

extern "C" void kernel_launch(void* const* d_in, const int* in_sizes, int n_in,
                              void* d_out, int out_size) {
    const float* r    = (const float*)d_in[0];
    const float* B_re = (const float*)d_in[1];
    const float* B_im = (const float*)d_in[2];
    const float* C_re = (const float*)d_in[3];
    const float* C_im = (const float*)d_in[4];
    const float* P_re = (const float*)d_in[5];
    const float* P_im = (const float*)d_in[6];
    const float* Q_re = (const float*)d_in[7];
    const float* Q_im = (const float*)d_in[8];
    const float* dre  = (const float*)d_in[9];
    const float* dim_ = (const float*)d_in[10];
    const float* step = (const float*)d_in[11];
    const float* Dp   = (const float*)d_in[12];
    float* out = (float*)d_out;

    static int attr_done = 0;
    if (!attr_done) {
        cudaFuncSetAttribute(k_kf,   cudaFuncAttributeMaxDynamicSharedMemorySize, 2 * BUFSZ * sizeof(float2));
        cudaFuncSetAttribute(k_conv, cudaFuncAttributeMaxDynamicSharedMemorySize, 2 * BUFSZ * sizeof(float2));
        attr_done = 1;
    }

    k_tw<<<5, 256>>>();
    k_prep<<<8, 256>>>(B_re, B_im, P_re, P_im, Q_re, Q_im, dre, dim_, step);
    k_tri<<<dim3(LL / 32, 16, BB), 256>>>(r);
    k_ar<<<dim3(LL / 64, HH / 64), 256>>>(C_re, C_im, B_re, B_im, P_re, P_im);
    k_kf<<<HH, 512, 2 * BUFSZ * sizeof(float2)>>>();
    k_conv<<<dim3(HH / 2, BB), 512, 2 * BUFSZ * sizeof(float2)>>>(Dp);
    k_tro<<<dim3(LL / 32, 16, BB), 256>>>(out);
}

// round 13
// speedup vs baseline: 1.1872x; 1.0521x over previous
#include <cuda_runtime.h>
#include <math.h>

#define BB 8
#define HH 1024
#define LL 2048
#define NN 64
#define NF 4096
#define PADI(i) ((i) + ((i) >> 4))
#define BUFSZ 4352

__device__ float2 g_cden[LL * NN];
__device__ float4 g_cd4[LL * NN];              // (cden, c*cden) interleaved
__device__ float2 g_fl[LL];
__device__ float2 g_cl[LL];
__device__ float2 g_ar[(size_t)HH * LL];       // 16 MB
__device__ float2 g_Kf[(size_t)HH * NF];       // 32 MB (pre-scaled by 1/NF)
__device__ float2 g_tw[1025];
__device__ float2 g_rT[(size_t)BB * 512 * LL]; // 64 MB
__device__ float2 g_oT[(size_t)BB * 512 * LL]; // 64 MB

__device__ __forceinline__ float2 cmulf(float2 a, float2 b) {
    return make_float2(fmaf(a.x, b.x, -a.y * b.y), fmaf(a.x, b.y, a.y * b.x));
}
__device__ __forceinline__ void cfma(float2& acc, float2 a, float2 b) {
    acc.x = fmaf(a.x, b.x, fmaf(-a.y, b.y, acc.x));
    acc.y = fmaf(a.x, b.y, fmaf(a.y, b.x, acc.y));
}
__device__ __forceinline__ float2 cadd(float2 a, float2 b) { return make_float2(a.x + b.x, a.y + b.y); }
__device__ __forceinline__ float2 csub(float2 a, float2 b) { return make_float2(a.x - b.x, a.y - b.y); }

template <int DIR>
__device__ __forceinline__ void dft4v(float2 v[4]) {
    float2 apc = cadd(v[0], v[2]), amc = csub(v[0], v[2]);
    float2 bpd = cadd(v[1], v[3]), bmd = csub(v[1], v[3]);
    float2 jb = make_float2(-(float)DIR * bmd.y, (float)DIR * bmd.x);
    v[0] = cadd(apc, bpd); v[1] = cadd(amc, jb);
    v[2] = csub(apc, bpd); v[3] = csub(amc, jb);
}

template <int DIR>
__device__ __forceinline__ void dft8(float2 v[8]) {
    float2 e[4] = {v[0], v[2], v[4], v[6]};
    float2 o[4] = {v[1], v[3], v[5], v[7]};
    dft4v<DIR>(e);
    dft4v<DIR>(o);
    const float R2 = 0.70710678118654752440f;
    float2 w1 = make_float2(R2, (float)DIR * R2);
    float2 w3 = make_float2(-R2, (float)DIR * R2);
    float2 o1 = cmulf(o[1], w1);
    float2 o2 = make_float2(-(float)DIR * o[2].y, (float)DIR * o[2].x);
    float2 o3 = cmulf(o[3], w3);
    v[0] = cadd(e[0], o[0]); v[4] = csub(e[0], o[0]);
    v[1] = cadd(e[1], o1);   v[5] = csub(e[1], o1);
    v[2] = cadd(e[2], o2);   v[6] = csub(e[2], o2);
    v[3] = cadd(e[3], o3);   v[7] = csub(e[3], o3);
}

// multiply by exp(DIR * 2*pi*i * e/16), e in [0,9] compile-time
template <int DIR>
__device__ __forceinline__ float2 w16mul(float2 a, int e) {
    const float tc[10] = {1.f, 0.92387953251128675613f, 0.70710678118654752440f, 0.38268343236508977173f,
                          0.f, -0.38268343236508977173f, -0.70710678118654752440f, -0.92387953251128675613f,
                          -1.f, -0.92387953251128675613f};
    const float ts[10] = {0.f, 0.38268343236508977173f, 0.70710678118654752440f, 0.92387953251128675613f,
                          1.f, 0.92387953251128675613f, 0.70710678118654752440f, 0.38268343236508977173f,
                          0.f, -0.38268343236508977173f};
    if (e == 0) return a;
    return cmulf(a, make_float2(tc[e], (float)DIR * ts[e]));
}

// natural-order 16-point DFT (4x4 Cooley-Tukey), DIR=-1 fwd / +1 inv
template <int DIR>
__device__ __forceinline__ void dft16(float2 v[16]) {
    float2 t[16];
#pragma unroll
    for (int q = 0; q < 4; q++) {
        float2 a = v[q], b = v[q + 4], c = v[q + 8], d = v[q + 12];
        float2 apc = cadd(a, c), amc = csub(a, c);
        float2 bpd = cadd(b, d), bmd = csub(b, d);
        float2 jb = make_float2(-(float)DIR * bmd.y, (float)DIR * bmd.x);
        t[0 + q]  = cadd(apc, bpd);
        t[4 + q]  = w16mul<DIR>(cadd(amc, jb), q);
        t[8 + q]  = w16mul<DIR>(csub(apc, bpd), 2 * q);
        t[12 + q] = w16mul<DIR>(csub(amc, jb), 3 * q);
    }
#pragma unroll
    for (int p = 0; p < 4; p++) {
        float2 a = t[4 * p], b = t[4 * p + 1], c = t[4 * p + 2], d = t[4 * p + 3];
        float2 apc = cadd(a, c), amc = csub(a, c);
        float2 bpd = cadd(b, d), bmd = csub(b, d);
        float2 jb = make_float2(-(float)DIR * bmd.y, (float)DIR * bmd.x);
        v[p]      = cadd(apc, bpd);
        v[p + 4]  = cadd(amc, jb);
        v[p + 8]  = csub(apc, bpd);
        v[p + 12] = csub(amc, jb);
    }
}

// store 16 results with twiddle w1^k (log-depth power ladder)
__device__ __forceinline__ void store16(float2* dst, float2 v[16], int ob, int ls, float2 w1) {
    float2 w[16];
    w[0] = make_float2(1.f, 0.f);
    w[1] = w1;
#pragma unroll
    for (int k = 2; k < 16; k++) w[k] = cmulf(w[k >> 1], w[k - (k >> 1)]);
    dst[PADI(ob)] = v[0];
#pragma unroll
    for (int k = 1; k < 16; k++) dst[PADI(ob + (k << ls))] = cmulf(v[k], w[k]);
}

__device__ __forceinline__ void pass_store(float2* dst, float2 v[8], int ob, int ls, float2 w1) {
    dst[PADI(ob)] = v[0];
    float2 wk = w1;
    dst[PADI(ob + (1 << ls))] = cmulf(v[1], wk);
#pragma unroll
    for (int k = 2; k < 8; k++) {
        wk = cmulf(wk, w1);
        dst[PADI(ob + (k << ls))] = cmulf(v[k], wk);
    }
}

template <int NTOT, int DIR, int NT>
__device__ __forceinline__ void fft_passes(float2*& src, float2*& dst, int nn, int ls, int nnEnd) {
    while (nn >= nnEnd) {
        int tstep = NF / nn;
        for (int idx = threadIdx.x; idx < (NTOT >> 3); idx += NT) {
            int p = idx >> ls;
            int q = idx & ((1 << ls) - 1);
            int base = q + (p << ls);
            float2 v[8];
#pragma unroll
            for (int j = 0; j < 8; j++) v[j] = src[PADI(base + j * (NTOT >> 3))];
            dft8<DIR>(v);
            float2 w1 = __ldg(&g_tw[p * tstep]);
            if (DIR > 0) w1.y = -w1.y;
            pass_store(dst, v, q + (p << (ls + 3)), ls, w1);
        }
        __syncthreads();
        float2* t = src; src = dst; dst = t;
        nn >>= 3;
        ls += 3;
    }
}

template <int NFFT, int DIR, int NT>
__device__ __forceinline__ void block_fft(float2* x, float2* y) {
    float2* src = x;
    float2* dst = y;
    fft_passes<NFFT, DIR, NT>(src, dst, NFFT, 0, 8);
    if (NFFT == LL) {  // radix-4 tail, nn=4, ls=9
        for (int idx = threadIdx.x; idx < (NFFT >> 2); idx += NT) {
            float2 v[4];
#pragma unroll
            for (int j = 0; j < 4; j++) v[j] = src[PADI(idx + j * (NFFT >> 2))];
            dft4v<DIR>(v);
#pragma unroll
            for (int k = 0; k < 4; k++) dst[PADI(idx + (k << 9))] = v[k];
        }
        __syncthreads();
    }
}

__global__ void k_tw() {
    int j = blockIdx.x * blockDim.x + threadIdx.x;
    if (j > 1024) return;
    float ang = -6.28318530717958647692f * (float)j / (float)NF;
    float s, c;
    sincosf(ang, &s, &c);
    g_tw[j] = make_float2(c, s);
}

__global__ void k_prep(const float* __restrict__ B_re, const float* __restrict__ B_im,
                       const float* __restrict__ P_re, const float* __restrict__ P_im,
                       const float* __restrict__ Q_re, const float* __restrict__ Q_im,
                       const float* __restrict__ dre,  const float* __restrict__ dim_,
                       const float* __restrict__ step) {
    int l = blockIdx.x * blockDim.x + threadIdx.x;
    if (l >= LL) return;
    float st = fmaxf(step[0], 1e-6f);
    float ang = (-6.28318530717958647692f * (float)l) / (float)LL;
    float zs, zc;
    sincosf(ang, &zs, &zc);
    float2 omz = make_float2(1.0f - zc, -zs);
    float2 opz = make_float2(1.0f + zc, zs);
    float invp = 1.0f / (opz.x * opz.x + opz.y * opz.y);
    float2 q = cmulf(omz, make_float2(opz.x, -opz.y));
    float2 g = make_float2((2.0f / st) * q.x * invp, (2.0f / st) * q.y * invp);
    float2 k10 = make_float2(0.f, 0.f), k11 = make_float2(0.f, 0.f);
    for (int n = 0; n < NN; n++) {
        float2 den = make_float2(g.x - dre[n], g.y - dim_[n]);
        float di = 1.0f / (den.x * den.x + den.y * den.y);
        float2 cd = make_float2(den.x * di, -den.y * di);
        g_cden[(size_t)l * NN + n] = cd;
        float2 Bv = make_float2(B_re[n], B_im[n]);
        float2 Pv = make_float2(P_re[n], P_im[n]);
        float2 Qv = make_float2(Q_re[n], Q_im[n]);
        cfma(k10, cmulf(Qv, Bv), cd);
        cfma(k11, cmulf(Qv, Pv), cd);
    }
    float2 onep = make_float2(1.0f + k11.x, k11.y);
    float i2 = 1.0f / (onep.x * onep.x + onep.y * onep.y);
    float2 c = cmulf(k10, make_float2(onep.x * i2, -onep.y * i2));
    g_fl[l] = make_float2(2.0f * opz.x * invp, -2.0f * opz.y * invp);
    g_cl[l] = c;
    for (int n = 0; n < NN; n++) {
        float2 cd = g_cden[(size_t)l * NN + n];
        float2 cd2 = cmulf(c, cd);
        g_cd4[(size_t)l * NN + n] = make_float4(cd.x, cd.y, cd2.x, cd2.y);
    }
}

// K2: at_roots[h,l] = f[l] * sum_n (CB[h,n]*cden[l,n] - CP[h,n]*cden2[l,n])
// tile 64l x 64h, STRIDED 4x4 microtile (stride 16 -> conflict-free LDS.128)
__global__ void __launch_bounds__(256, 3) k_ar(const float* __restrict__ C_re, const float* __restrict__ C_im,
                                               const float* __restrict__ B_re, const float* __restrict__ B_im,
                                               const float* __restrict__ P_re, const float* __restrict__ P_im) {
    __shared__ float4 sCD[16 * 65];   // [n][l]: (cden, cden2)
    __shared__ float4 sBP[16 * 65];   // [n][h]: (CB, CP)
    int l0 = blockIdx.x * 64;
    int h0 = blockIdx.y * 64;
    int tid = threadIdx.x;
    int tl = tid & 15;
    int th = tid >> 4;
    float2 acc[4][4];
#pragma unroll
    for (int ih = 0; ih < 4; ih++)
#pragma unroll
        for (int il = 0; il < 4; il++) acc[ih][il] = make_float2(0.f, 0.f);

    for (int nc = 0; nc < NN; nc += 16) {
        __syncthreads();
        for (int i = tid; i < 64 * 16; i += 256) {
            int row = i >> 4, n = i & 15;
            int gn = nc + n;
            sCD[n * 65 + row] = g_cd4[(size_t)(l0 + row) * NN + gn];
            float2 Cv = make_float2(C_re[(size_t)(h0 + row) * NN + gn], C_im[(size_t)(h0 + row) * NN + gn]);
            float2 cb = cmulf(Cv, make_float2(B_re[gn], B_im[gn]));
            float2 cp = cmulf(Cv, make_float2(P_re[gn], P_im[gn]));
            sBP[n * 65 + row] = make_float4(cb.x, cb.y, cp.x, cp.y);
        }
        __syncthreads();
#pragma unroll
        for (int n = 0; n < 16; n++) {
            float4 cd[4], bp[4];
#pragma unroll
            for (int il = 0; il < 4; il++) cd[il] = sCD[n * 65 + tl + 16 * il];
#pragma unroll
            for (int ih = 0; ih < 4; ih++) bp[ih] = sBP[n * 65 + th + 16 * ih];
#pragma unroll
            for (int ih = 0; ih < 4; ih++)
#pragma unroll
                for (int il = 0; il < 4; il++) {
                    float2& a = acc[ih][il];
                    a.x = fmaf(bp[ih].x, cd[il].x, a.x);
                    a.x = fmaf(-bp[ih].y, cd[il].y, a.x);
                    a.x = fmaf(-bp[ih].z, cd[il].z, a.x);
                    a.x = fmaf(bp[ih].w, cd[il].w, a.x);
                    a.y = fmaf(bp[ih].x, cd[il].y, a.y);
                    a.y = fmaf(bp[ih].y, cd[il].x, a.y);
                    a.y = fmaf(-bp[ih].z, cd[il].w, a.y);
                    a.y = fmaf(-bp[ih].w, cd[il].z, a.y);
                }
        }
    }
    float2 fl[4];
#pragma unroll
    for (int il = 0; il < 4; il++) fl[il] = g_fl[l0 + tl + 16 * il];
#pragma unroll
    for (int ih = 0; ih < 4; ih++) {
        int h = h0 + th + 16 * ih;
#pragma unroll
        for (int il = 0; il < 4; il++) {
            g_ar[(size_t)h * LL + l0 + tl + 16 * il] = cmulf(fl[il], acc[ih][il]);
        }
    }
}

__global__ void __launch_bounds__(512, 2) k_kf() {
    extern __shared__ float2 sh2[];
    float2* A = sh2;
    float2* Bb = sh2 + BUFSZ;
    int h = blockIdx.x;
    for (int l = threadIdx.x; l < LL; l += 512) A[PADI(l)] = g_ar[(size_t)h * LL + l];
    __syncthreads();
    block_fft<LL, 1, 512>(A, Bb);
    float kv[4];
#pragma unroll
    for (int i = 0; i < 4; i++) {
        int l = threadIdx.x + i * 512;
        kv[i] = A[PADI(l)].x * (1.0f / (float)LL);
    }
    __syncthreads();
#pragma unroll
    for (int i = 0; i < 4; i++) {
        int l = threadIdx.x + i * 512;
        A[PADI(l)] = make_float2(kv[i], 0.f);
        A[PADI(l + LL)] = make_float2(0.f, 0.f);
    }
    __syncthreads();
    block_fft<NF, -1, 512>(A, Bb);
    const float sc = 1.0f / (float)NF;   // pre-scale spectrum
    for (int k = threadIdx.x; k < NF; k += 512) {
        float2 v = A[PADI(k)];
        g_Kf[(size_t)h * NF + k] = make_float2(v.x * sc, v.y * sc);
    }
}

__global__ void __launch_bounds__(256) k_tri(const float* __restrict__ r) {
    __shared__ float2 s[32][33];
    int b = blockIdx.z, l0 = blockIdx.x * 32, hp0 = blockIdx.y * 32;
    const float2* r2 = (const float2*)(r + (size_t)b * LL * HH);
    int lane = threadIdx.x & 31, row = threadIdx.x >> 5;
#pragma unroll
    for (int k = 0; k < 4; k++) {
        int rr = row + 8 * k;
        s[rr][lane] = r2[(size_t)(l0 + rr) * 512 + hp0 + lane];
    }
    __syncthreads();
    float2* dst = g_rT + (size_t)b * 512 * LL;
#pragma unroll
    for (int k = 0; k < 4; k++) {
        int rr = row + 8 * k;
        dst[(size_t)(hp0 + rr) * LL + l0 + lane] = s[lane][rr];
    }
}

__global__ void __launch_bounds__(256) k_tro(float* __restrict__ out) {
    __shared__ float2 s[32][33];
    int b = blockIdx.z, l0 = blockIdx.x * 32, hp0 = blockIdx.y * 32;
    const float2* src = g_oT + (size_t)b * 512 * LL;
    int lane = threadIdx.x & 31, row = threadIdx.x >> 5;
#pragma unroll
    for (int k = 0; k < 4; k++) {
        int rr = row + 8 * k;
        s[rr][lane] = src[(size_t)(hp0 + rr) * LL + l0 + lane];
    }
    __syncthreads();
    float2* o2 = (float2*)(out + (size_t)b * LL * HH);
#pragma unroll
    for (int k = 0; k < 4; k++) {
        int rr = row + 8 * k;
        o2[(size_t)(l0 + rr) * 512 + hp0 + lane] = s[lane][rr];
    }
}

// K4: FFT convolution, radix-16 (3 stages), 256 threads x 16 elems
__global__ void __launch_bounds__(256, 2) k_conv(const float* __restrict__ Dp) {
    extern __shared__ float2 sh2[];
    float2* A = sh2;
    float2* Bb = sh2 + BUFSZ;
    int hp = blockIdx.x;
    int b = blockIdx.y;
    int tid = threadIdx.x;
    float Dv = Dp[0];
    const float2* rp = g_rT + ((size_t)b * 512 + hp) * LL;
    {   // forward stage 1 (fused load, nn=4096, ls=0, p=tid; upper half zero)
        float2 v[16];
#pragma unroll
        for (int j = 0; j < 8; j++) {
            v[j] = rp[tid + j * 256];
            v[j + 8] = make_float2(0.f, 0.f);
        }
        dft16<-1>(v);
        store16(A, v, tid << 4, 0, __ldg(&g_tw[tid]));
    }
    __syncthreads();
    {   // forward stage 2 (nn=256, ls=4)
        int p = tid >> 4, q = tid & 15;
        float2 v[16];
#pragma unroll
        for (int j = 0; j < 16; j++) v[j] = A[PADI(tid + j * 256)];
        dft16<-1>(v);
        store16(Bb, v, q + (p << 8), 4, __ldg(&g_tw[p * 16]));
    }
    __syncthreads();
    {   // forward stage 3 (nn=16, ls=8, p=0, twiddle-free) -> natural order in A
        float2 v[16];
#pragma unroll
        for (int j = 0; j < 16; j++) v[j] = Bb[PADI(tid + j * 256)];
        dft16<-1>(v);
#pragma unroll
        for (int k = 0; k < 16; k++) A[PADI(tid + (k << 8))] = v[k];
    }
    __syncthreads();
    {   // untangle + per-channel Kf multiply (in-place on A)
        const float2* K0 = g_Kf + (size_t)(2 * hp) * NF;
        const float2* K1 = K0 + NF;
        for (int k = tid; k <= NF / 2; k += 256) {
            int km = (NF - k) & (NF - 1);
            float2 a = A[PADI(k)];
            float2 bc = A[PADI(km)]; bc.y = -bc.y;
            float2 X0 = make_float2(0.5f * (a.x + bc.x), 0.5f * (a.y + bc.y));
            float2 dd = make_float2(0.5f * (a.x - bc.x), 0.5f * (a.y - bc.y));
            float2 X1 = make_float2(dd.y, -dd.x);
            float2 t0 = cmulf(X0, __ldg(&K0[k]));
            float2 t1 = cmulf(X1, __ldg(&K1[k]));
            A[PADI(k)]  = make_float2(t0.x - t1.y, t0.y + t1.x);
            A[PADI(km)] = make_float2(t0.x + t1.y, -t0.y + t1.x);
        }
    }
    __syncthreads();
    {   // inverse stage 1 (ls=0, p=tid)
        float2 v[16];
#pragma unroll
        for (int j = 0; j < 16; j++) v[j] = A[PADI(tid + j * 256)];
        dft16<1>(v);
        float2 w1 = __ldg(&g_tw[tid]); w1.y = -w1.y;
        store16(Bb, v, tid << 4, 0, w1);
    }
    __syncthreads();
    {   // inverse stage 2 (ls=4)
        int p = tid >> 4, q = tid & 15;
        float2 v[16];
#pragma unroll
        for (int j = 0; j < 16; j++) v[j] = Bb[PADI(tid + j * 256)];
        dft16<1>(v);
        float2 w1 = __ldg(&g_tw[p * 16]); w1.y = -w1.y;
        store16(A, v, q + (p << 8), 4, w1);
    }
    __syncthreads();
    {   // inverse stage 3 (p=0, twiddle-free) fused with epilogue
        float2 v[16];
#pragma unroll
        for (int j = 0; j < 16; j++) v[j] = A[PADI(tid + j * 256)];
        dft16<1>(v);
        float2* op = g_oT + ((size_t)b * 512 + hp) * LL;
#pragma unroll
        for (int k = 0; k < 8; k++) {         // l = tid + k*256 < 2048
            float2 rvk = rp[tid + k * 256];
            float y0 = fmaf(Dv, rvk.x, v[k].x);   // Kf pre-scaled by 1/NF
            float y1 = fmaf(Dv, rvk.y, v[k].y);
            float g0 = 0.5f * y0 * (1.0f + erff(y0 * 0.70710678118654752f));
            float g1 = 0.5f * y1 * (1.0f + erff(y1 * 0.70710678118654752f));
            op[tid + k * 256] = make_float2(g0, g1);
        }
    }
}

extern "C" void kernel_launch(void* const* d_in, const int* in_sizes, int n_in,
                              void* d_out, int out_size) {
    const float* r    = (const float*)d_in[0];
    const float* B_re = (const float*)d_in[1];
    const float* B_im = (const float*)d_in[2];
    const float* C_re = (const float*)d_in[3];
    const float* C_im = (const float*)d_in[4];
    const float* P_re = (const float*)d_in[5];
    const float* P_im = (const float*)d_in[6];
    const float* Q_re = (const float*)d_in[7];
    const float* Q_im = (const float*)d_in[8];
    const float* dre  = (const float*)d_in[9];
    const float* dim_ = (const float*)d_in[10];
    const float* step = (const float*)d_in[11];
    const float* Dp   = (const float*)d_in[12];
    float* out = (float*)d_out;

    static int attr_done = 0;
    if (!attr_done) {
        cudaFuncSetAttribute(k_kf,   cudaFuncAttributeMaxDynamicSharedMemorySize, 2 * BUFSZ * sizeof(float2));
        cudaFuncSetAttribute(k_conv, cudaFuncAttributeMaxDynamicSharedMemorySize, 2 * BUFSZ * sizeof(float2));
        attr_done = 1;
    }

    k_tw<<<5, 256>>>();
    k_prep<<<8, 256>>>(B_re, B_im, P_re, P_im, Q_re, Q_im, dre, dim_, step);
    k_tri<<<dim3(LL / 32, 16, BB), 256>>>(r);
    k_ar<<<dim3(LL / 64, HH / 64), 256>>>(C_re, C_im, B_re, B_im, P_re, P_im);
    k_kf<<<HH, 512, 2 * BUFSZ * sizeof(float2)>>>();
    k_conv<<<dim3(HH / 2, BB), 256, 2 * BUFSZ * sizeof(float2)>>>(Dp);
    k_tro<<<dim3(LL / 32, 16, BB), 256>>>(out);
}

// round 14
// speedup vs baseline: 1.3259x; 1.1169x over previous
#include <cuda_runtime.h>
#include <math.h>

#define BB 8
#define HH 1024
#define LL 2048
#define NN 64
#define NF 4096
#define PADI(i) ((i) + ((i) >> 4))
#define BUFSZ 4352

__device__ float2 g_cden[LL * NN];
__device__ float4 g_cd4[LL * NN];              // (cden, c*cden) interleaved
__device__ float2 g_fl[LL];
__device__ float2 g_cl[LL];
__device__ float2 g_ar[(size_t)HH * LL];       // 16 MB
__device__ float2 g_Kf[(size_t)HH * NF];       // 32 MB (pre-scaled by 1/NF)
__device__ float2 g_tw[1025];
__device__ float2 g_rT[(size_t)BB * 512 * LL]; // 64 MB
__device__ float2 g_oT[(size_t)BB * 512 * LL]; // 64 MB

__device__ __forceinline__ float2 cmulf(float2 a, float2 b) {
    return make_float2(fmaf(a.x, b.x, -a.y * b.y), fmaf(a.x, b.y, a.y * b.x));
}
__device__ __forceinline__ void cfma(float2& acc, float2 a, float2 b) {
    acc.x = fmaf(a.x, b.x, fmaf(-a.y, b.y, acc.x));
    acc.y = fmaf(a.x, b.y, fmaf(a.y, b.x, acc.y));
}
__device__ __forceinline__ float2 cadd(float2 a, float2 b) { return make_float2(a.x + b.x, a.y + b.y); }
__device__ __forceinline__ float2 csub(float2 a, float2 b) { return make_float2(a.x - b.x, a.y - b.y); }

template <int DIR>
__device__ __forceinline__ void dft4v(float2 v[4]) {
    float2 apc = cadd(v[0], v[2]), amc = csub(v[0], v[2]);
    float2 bpd = cadd(v[1], v[3]), bmd = csub(v[1], v[3]);
    float2 jb = make_float2(-(float)DIR * bmd.y, (float)DIR * bmd.x);
    v[0] = cadd(apc, bpd); v[1] = cadd(amc, jb);
    v[2] = csub(apc, bpd); v[3] = csub(amc, jb);
}

template <int DIR>
__device__ __forceinline__ void dft8(float2 v[8]) {
    float2 e[4] = {v[0], v[2], v[4], v[6]};
    float2 o[4] = {v[1], v[3], v[5], v[7]};
    dft4v<DIR>(e);
    dft4v<DIR>(o);
    const float R2 = 0.70710678118654752440f;
    float2 w1 = make_float2(R2, (float)DIR * R2);
    float2 w3 = make_float2(-R2, (float)DIR * R2);
    float2 o1 = cmulf(o[1], w1);
    float2 o2 = make_float2(-(float)DIR * o[2].y, (float)DIR * o[2].x);
    float2 o3 = cmulf(o[3], w3);
    v[0] = cadd(e[0], o[0]); v[4] = csub(e[0], o[0]);
    v[1] = cadd(e[1], o1);   v[5] = csub(e[1], o1);
    v[2] = cadd(e[2], o2);   v[6] = csub(e[2], o2);
    v[3] = cadd(e[3], o3);   v[7] = csub(e[3], o3);
}

// multiply by exp(DIR * 2*pi*i * e/16), e in [0,9] compile-time
template <int DIR>
__device__ __forceinline__ float2 w16mul(float2 a, int e) {
    const float tc[10] = {1.f, 0.92387953251128675613f, 0.70710678118654752440f, 0.38268343236508977173f,
                          0.f, -0.38268343236508977173f, -0.70710678118654752440f, -0.92387953251128675613f,
                          -1.f, -0.92387953251128675613f};
    const float ts[10] = {0.f, 0.38268343236508977173f, 0.70710678118654752440f, 0.92387953251128675613f,
                          1.f, 0.92387953251128675613f, 0.70710678118654752440f, 0.38268343236508977173f,
                          0.f, -0.38268343236508977173f};
    if (e == 0) return a;
    return cmulf(a, make_float2(tc[e], (float)DIR * ts[e]));
}

// natural-order 16-point DFT (4x4 Cooley-Tukey), DIR=-1 fwd / +1 inv
template <int DIR>
__device__ __forceinline__ void dft16(float2 v[16]) {
    float2 t[16];
#pragma unroll
    for (int q = 0; q < 4; q++) {
        float2 a = v[q], b = v[q + 4], c = v[q + 8], d = v[q + 12];
        float2 apc = cadd(a, c), amc = csub(a, c);
        float2 bpd = cadd(b, d), bmd = csub(b, d);
        float2 jb = make_float2(-(float)DIR * bmd.y, (float)DIR * bmd.x);
        t[0 + q]  = cadd(apc, bpd);
        t[4 + q]  = w16mul<DIR>(cadd(amc, jb), q);
        t[8 + q]  = w16mul<DIR>(csub(apc, bpd), 2 * q);
        t[12 + q] = w16mul<DIR>(csub(amc, jb), 3 * q);
    }
#pragma unroll
    for (int p = 0; p < 4; p++) {
        float2 a = t[4 * p], b = t[4 * p + 1], c = t[4 * p + 2], d = t[4 * p + 3];
        float2 apc = cadd(a, c), amc = csub(a, c);
        float2 bpd = cadd(b, d), bmd = csub(b, d);
        float2 jb = make_float2(-(float)DIR * bmd.y, (float)DIR * bmd.x);
        v[p]      = cadd(apc, bpd);
        v[p + 4]  = cadd(amc, jb);
        v[p + 8]  = csub(apc, bpd);
        v[p + 12] = csub(amc, jb);
    }
}

// store 16 results with twiddle w1^k (log-depth power ladder)
__device__ __forceinline__ void store16(float2* dst, float2 v[16], int ob, int ls, float2 w1) {
    float2 w[16];
    w[0] = make_float2(1.f, 0.f);
    w[1] = w1;
#pragma unroll
    for (int k = 2; k < 16; k++) w[k] = cmulf(w[k >> 1], w[k - (k >> 1)]);
    dst[PADI(ob)] = v[0];
#pragma unroll
    for (int k = 1; k < 16; k++) dst[PADI(ob + (k << ls))] = cmulf(v[k], w[k]);
}

__global__ void k_tw() {
    int j = blockIdx.x * blockDim.x + threadIdx.x;
    if (j > 1024) return;
    float ang = -6.28318530717958647692f * (float)j / (float)NF;
    float s, c;
    sincosf(ang, &s, &c);
    g_tw[j] = make_float2(c, s);
}

__global__ void k_prep(const float* __restrict__ B_re, const float* __restrict__ B_im,
                       const float* __restrict__ P_re, const float* __restrict__ P_im,
                       const float* __restrict__ Q_re, const float* __restrict__ Q_im,
                       const float* __restrict__ dre,  const float* __restrict__ dim_,
                       const float* __restrict__ step) {
    int l = blockIdx.x * blockDim.x + threadIdx.x;
    if (l >= LL) return;
    float st = fmaxf(step[0], 1e-6f);
    float ang = (-6.28318530717958647692f * (float)l) / (float)LL;
    float zs, zc;
    sincosf(ang, &zs, &zc);
    float2 omz = make_float2(1.0f - zc, -zs);
    float2 opz = make_float2(1.0f + zc, zs);
    float invp = 1.0f / (opz.x * opz.x + opz.y * opz.y);
    float2 q = cmulf(omz, make_float2(opz.x, -opz.y));
    float2 g = make_float2((2.0f / st) * q.x * invp, (2.0f / st) * q.y * invp);
    float2 k10 = make_float2(0.f, 0.f), k11 = make_float2(0.f, 0.f);
    for (int n = 0; n < NN; n++) {
        float2 den = make_float2(g.x - dre[n], g.y - dim_[n]);
        float di = 1.0f / (den.x * den.x + den.y * den.y);
        float2 cd = make_float2(den.x * di, -den.y * di);
        g_cden[(size_t)l * NN + n] = cd;
        float2 Bv = make_float2(B_re[n], B_im[n]);
        float2 Pv = make_float2(P_re[n], P_im[n]);
        float2 Qv = make_float2(Q_re[n], Q_im[n]);
        cfma(k10, cmulf(Qv, Bv), cd);
        cfma(k11, cmulf(Qv, Pv), cd);
    }
    float2 onep = make_float2(1.0f + k11.x, k11.y);
    float i2 = 1.0f / (onep.x * onep.x + onep.y * onep.y);
    float2 c = cmulf(k10, make_float2(onep.x * i2, -onep.y * i2));
    g_fl[l] = make_float2(2.0f * opz.x * invp, -2.0f * opz.y * invp);
    g_cl[l] = c;
    for (int n = 0; n < NN; n++) {
        float2 cd = g_cden[(size_t)l * NN + n];
        float2 cd2 = cmulf(c, cd);
        g_cd4[(size_t)l * NN + n] = make_float4(cd.x, cd.y, cd2.x, cd2.y);
    }
}

// K2: at_roots[h,l] = f[l] * sum_n (CB[h,n]*cden[l,n] - CP[h,n]*cden2[l,n])
// tile 64l x 64h, STRIDED 4x4 microtile (stride 16 -> conflict-free LDS.128)
__global__ void __launch_bounds__(256, 3) k_ar(const float* __restrict__ C_re, const float* __restrict__ C_im,
                                               const float* __restrict__ B_re, const float* __restrict__ B_im,
                                               const float* __restrict__ P_re, const float* __restrict__ P_im) {
    __shared__ float4 sCD[16 * 65];   // [n][l]: (cden, cden2)
    __shared__ float4 sBP[16 * 65];   // [n][h]: (CB, CP)
    int l0 = blockIdx.x * 64;
    int h0 = blockIdx.y * 64;
    int tid = threadIdx.x;
    int tl = tid & 15;
    int th = tid >> 4;
    float2 acc[4][4];
#pragma unroll
    for (int ih = 0; ih < 4; ih++)
#pragma unroll
        for (int il = 0; il < 4; il++) acc[ih][il] = make_float2(0.f, 0.f);

    for (int nc = 0; nc < NN; nc += 16) {
        __syncthreads();
        for (int i = tid; i < 64 * 16; i += 256) {
            int row = i >> 4, n = i & 15;
            int gn = nc + n;
            sCD[n * 65 + row] = g_cd4[(size_t)(l0 + row) * NN + gn];
            float2 Cv = make_float2(C_re[(size_t)(h0 + row) * NN + gn], C_im[(size_t)(h0 + row) * NN + gn]);
            float2 cb = cmulf(Cv, make_float2(B_re[gn], B_im[gn]));
            float2 cp = cmulf(Cv, make_float2(P_re[gn], P_im[gn]));
            sBP[n * 65 + row] = make_float4(cb.x, cb.y, cp.x, cp.y);
        }
        __syncthreads();
#pragma unroll
        for (int n = 0; n < 16; n++) {
            float4 cd[4], bp[4];
#pragma unroll
            for (int il = 0; il < 4; il++) cd[il] = sCD[n * 65 + tl + 16 * il];
#pragma unroll
            for (int ih = 0; ih < 4; ih++) bp[ih] = sBP[n * 65 + th + 16 * ih];
#pragma unroll
            for (int ih = 0; ih < 4; ih++)
#pragma unroll
                for (int il = 0; il < 4; il++) {
                    float2& a = acc[ih][il];
                    a.x = fmaf(bp[ih].x, cd[il].x, a.x);
                    a.x = fmaf(-bp[ih].y, cd[il].y, a.x);
                    a.x = fmaf(-bp[ih].z, cd[il].z, a.x);
                    a.x = fmaf(bp[ih].w, cd[il].w, a.x);
                    a.y = fmaf(bp[ih].x, cd[il].y, a.y);
                    a.y = fmaf(bp[ih].y, cd[il].x, a.y);
                    a.y = fmaf(-bp[ih].z, cd[il].w, a.y);
                    a.y = fmaf(-bp[ih].w, cd[il].z, a.y);
                }
        }
    }
    float2 fl[4];
#pragma unroll
    for (int il = 0; il < 4; il++) fl[il] = g_fl[l0 + tl + 16 * il];
#pragma unroll
    for (int ih = 0; ih < 4; ih++) {
        int h = h0 + th + 16 * ih;
#pragma unroll
        for (int il = 0; il < 4; il++) {
            g_ar[(size_t)h * LL + l0 + tl + 16 * il] = cmulf(fl[il], acc[ih][il]);
        }
    }
}

// K3: kernel spectrum per channel, radix-16, fully fused boundaries.
// iFFT2048 (16,16,8) -> K in registers -> FFT4096 (16,16,16) -> g_Kf (scaled 1/NF)
__global__ void __launch_bounds__(256, 2) k_kf() {
    extern __shared__ float2 sh2[];
    float2* A = sh2;
    float2* Bb = sh2 + BUFSZ;
    int h = blockIdx.x;
    int tid = threadIdx.x;
    const float2* arp = g_ar + (size_t)h * LL;
    // iFFT2048 stage 1: nn=2048, ls=0, tstep=2 (128 butterflies), fused global load
    if (tid < 128) {
        float2 v[16];
#pragma unroll
        for (int j = 0; j < 16; j++) v[j] = arp[tid + j * 128];
        dft16<1>(v);
        float2 w1 = __ldg(&g_tw[tid * 2]); w1.y = -w1.y;
        store16(A, v, tid << 4, 0, w1);
    }
    __syncthreads();
    // iFFT2048 stage 2: nn=128, ls=4, tstep=32 (128 butterflies)
    if (tid < 128) {
        int p = tid >> 4, q = tid & 15;
        float2 v[16];
#pragma unroll
        for (int j = 0; j < 16; j++) v[j] = A[PADI(tid + j * 128)];
        dft16<1>(v);
        float2 w1 = __ldg(&g_tw[p * 32]); w1.y = -w1.y;
        store16(Bb, v, q + (p << 8), 4, w1);
    }
    __syncthreads();
    // iFFT2048 stage 3: radix-8, nn=8, ls=8, p=0 twiddle-free -> K in registers
    float kr[8];
    {
        float2 v[8];
#pragma unroll
        for (int j = 0; j < 8; j++) v[j] = Bb[PADI(tid + j * 256)];
        dft8<1>(v);
#pragma unroll
        for (int k = 0; k < 8; k++) kr[k] = v[k].x * (1.0f / (float)LL);  // K[tid + k*256]
    }
    // FFT4096 stage 1: nn=4096, ls=0, p=tid; input = K (j<8) and zero-pad (j>=8), all in regs
    {
        float2 v[16];
#pragma unroll
        for (int j = 0; j < 8; j++) {
            v[j] = make_float2(kr[j], 0.f);
            v[j + 8] = make_float2(0.f, 0.f);
        }
        dft16<-1>(v);
        store16(A, v, tid << 4, 0, __ldg(&g_tw[tid]));
    }
    __syncthreads();
    // FFT4096 stage 2: nn=256, ls=4, tstep=16
    {
        int p = tid >> 4, q = tid & 15;
        float2 v[16];
#pragma unroll
        for (int j = 0; j < 16; j++) v[j] = A[PADI(tid + j * 256)];
        dft16<-1>(v);
        store16(Bb, v, q + (p << 8), 4, __ldg(&g_tw[p * 16]));
    }
    __syncthreads();
    // FFT4096 stage 3: nn=16, p=0 twiddle-free, fused scaled store
    {
        float2 v[16];
#pragma unroll
        for (int j = 0; j < 16; j++) v[j] = Bb[PADI(tid + j * 256)];
        dft16<-1>(v);
        const float sc = 1.0f / (float)NF;
#pragma unroll
        for (int k = 0; k < 16; k++) {
            g_Kf[(size_t)h * NF + tid + (k << 8)] = make_float2(v[k].x * sc, v[k].y * sc);
        }
    }
}

__global__ void __launch_bounds__(256) k_tri(const float* __restrict__ r) {
    __shared__ float2 s[32][33];
    int b = blockIdx.z, l0 = blockIdx.x * 32, hp0 = blockIdx.y * 32;
    const float2* r2 = (const float2*)(r + (size_t)b * LL * HH);
    int lane = threadIdx.x & 31, row = threadIdx.x >> 5;
#pragma unroll
    for (int k = 0; k < 4; k++) {
        int rr = row + 8 * k;
        s[rr][lane] = r2[(size_t)(l0 + rr) * 512 + hp0 + lane];
    }
    __syncthreads();
    float2* dst = g_rT + (size_t)b * 512 * LL;
#pragma unroll
    for (int k = 0; k < 4; k++) {
        int rr = row + 8 * k;
        dst[(size_t)(hp0 + rr) * LL + l0 + lane] = s[lane][rr];
    }
}

__global__ void __launch_bounds__(256) k_tro(float* __restrict__ out) {
    __shared__ float2 s[32][33];
    int b = blockIdx.z, l0 = blockIdx.x * 32, hp0 = blockIdx.y * 32;
    const float2* src = g_oT + (size_t)b * 512 * LL;
    int lane = threadIdx.x & 31, row = threadIdx.x >> 5;
#pragma unroll
    for (int k = 0; k < 4; k++) {
        int rr = row + 8 * k;
        s[rr][lane] = src[(size_t)(hp0 + rr) * LL + l0 + lane];
    }
    __syncthreads();
    float2* o2 = (float2*)(out + (size_t)b * LL * HH);
#pragma unroll
    for (int k = 0; k < 4; k++) {
        int rr = row + 8 * k;
        o2[(size_t)(l0 + rr) * 512 + hp0 + lane] = s[lane][rr];
    }
}

// K4: FFT convolution, radix-16 (3 stages each way), untangle fused into inverse stage 1:
// V[i] = U[i]*Ka[i] + conj(U[N-i])*Kb[i],  Ka=(K0+K1)/2, Kb=(K0-K1)/2
__global__ void __launch_bounds__(256, 2) k_conv(const float* __restrict__ Dp) {
    extern __shared__ float2 sh2[];
    float2* A = sh2;
    float2* Bb = sh2 + BUFSZ;
    int hp = blockIdx.x;
    int b = blockIdx.y;
    int tid = threadIdx.x;
    float Dv = Dp[0];
    const float2* rp = g_rT + ((size_t)b * 512 + hp) * LL;
    {   // forward stage 1 (fused load, nn=4096, ls=0, p=tid; upper half zero)
        float2 v[16];
#pragma unroll
        for (int j = 0; j < 8; j++) {
            v[j] = rp[tid + j * 256];
            v[j + 8] = make_float2(0.f, 0.f);
        }
        dft16<-1>(v);
        store16(A, v, tid << 4, 0, __ldg(&g_tw[tid]));
    }
    __syncthreads();
    {   // forward stage 2 (nn=256, ls=4)
        int p = tid >> 4, q = tid & 15;
        float2 v[16];
#pragma unroll
        for (int j = 0; j < 16; j++) v[j] = A[PADI(tid + j * 256)];
        dft16<-1>(v);
        store16(Bb, v, q + (p << 8), 4, __ldg(&g_tw[p * 16]));
    }
    __syncthreads();
    {   // forward stage 3 (nn=16, ls=8, p=0, twiddle-free) -> natural order U in A
        float2 v[16];
#pragma unroll
        for (int j = 0; j < 16; j++) v[j] = Bb[PADI(tid + j * 256)];
        dft16<-1>(v);
#pragma unroll
        for (int k = 0; k < 16; k++) A[PADI(tid + (k << 8))] = v[k];
    }
    __syncthreads();
    {   // inverse stage 1 with FUSED untangle + Kf multiply (ls=0, p=tid)
        const float2* K0 = g_Kf + (size_t)(2 * hp) * NF;
        const float2* K1 = K0 + NF;
        float2 v[16];
#pragma unroll
        for (int j = 0; j < 16; j++) {
            int i = tid + j * 256;
            int mir = (NF - i) & (NF - 1);
            float2 U = A[PADI(i)];
            float2 Um = A[PADI(mir)]; Um.y = -Um.y;     // conj(U[N-i])
            float2 k0 = __ldg(&K0[i]);
            float2 k1 = __ldg(&K1[i]);
            float2 ka = make_float2(0.5f * (k0.x + k1.x), 0.5f * (k0.y + k1.y));
            float2 kb = make_float2(0.5f * (k0.x - k1.x), 0.5f * (k0.y - k1.y));
            v[j] = cadd(cmulf(U, ka), cmulf(Um, kb));
        }
        dft16<1>(v);
        float2 w1 = __ldg(&g_tw[tid]); w1.y = -w1.y;
        store16(Bb, v, tid << 4, 0, w1);
    }
    __syncthreads();
    {   // inverse stage 2 (ls=4)
        int p = tid >> 4, q = tid & 15;
        float2 v[16];
#pragma unroll
        for (int j = 0; j < 16; j++) v[j] = Bb[PADI(tid + j * 256)];
        dft16<1>(v);
        float2 w1 = __ldg(&g_tw[p * 16]); w1.y = -w1.y;
        store16(A, v, q + (p << 8), 4, w1);
    }
    __syncthreads();
    {   // inverse stage 3 (p=0, twiddle-free) fused with epilogue
        float2 v[16];
#pragma unroll
        for (int j = 0; j < 16; j++) v[j] = A[PADI(tid + j * 256)];
        dft16<1>(v);
        float2* op = g_oT + ((size_t)b * 512 + hp) * LL;
#pragma unroll
        for (int k = 0; k < 8; k++) {         // l = tid + k*256 < 2048
            float2 rvk = rp[tid + k * 256];
            float y0 = fmaf(Dv, rvk.x, v[k].x);   // Kf pre-scaled by 1/NF
            float y1 = fmaf(Dv, rvk.y, v[k].y);
            float g0 = 0.5f * y0 * (1.0f + erff(y0 * 0.70710678118654752f));
            float g1 = 0.5f * y1 * (1.0f + erff(y1 * 0.70710678118654752f));
            op[tid + k * 256] = make_float2(g0, g1);
        }
    }
}

extern "C" void kernel_launch(void* const* d_in, const int* in_sizes, int n_in,
                              void* d_out, int out_size) {
    const float* r    = (const float*)d_in[0];
    const float* B_re = (const float*)d_in[1];
    const float* B_im = (const float*)d_in[2];
    const float* C_re = (const float*)d_in[3];
    const float* C_im = (const float*)d_in[4];
    const float* P_re = (const float*)d_in[5];
    const float* P_im = (const float*)d_in[6];
    const float* Q_re = (const float*)d_in[7];
    const float* Q_im = (const float*)d_in[8];
    const float* dre  = (const float*)d_in[9];
    const float* dim_ = (const float*)d_in[10];
    const float* step = (const float*)d_in[11];
    const float* Dp   = (const float*)d_in[12];
    float* out = (float*)d_out;

    static int attr_done = 0;
    if (!attr_done) {
        cudaFuncSetAttribute(k_kf,   cudaFuncAttributeMaxDynamicSharedMemorySize, 2 * BUFSZ * sizeof(float2));
        cudaFuncSetAttribute(k_conv, cudaFuncAttributeMaxDynamicSharedMemorySize, 2 * BUFSZ * sizeof(float2));
        attr_done = 1;
    }

    k_tw<<<5, 256>>>();
    k_prep<<<8, 256>>>(B_re, B_im, P_re, P_im, Q_re, Q_im, dre, dim_, step);
    k_tri<<<dim3(LL / 32, 16, BB), 256>>>(r);
    k_ar<<<dim3(LL / 64, HH / 64), 256>>>(C_re, C_im, B_re, B_im, P_re, P_im);
    k_kf<<<HH, 256, 2 * BUFSZ * sizeof(float2)>>>();
    k_conv<<<dim3(HH / 2, BB), 256, 2 * BUFSZ * sizeof(float2)>>>(Dp);
    k_tro<<<dim3(LL / 32, 16, BB), 256>>>(out);
}